// round 1
// baseline (speedup 1.0000x reference)
#include <cuda_runtime.h>

#define B 32
#define S 4096
#define DIN 1024
#define DOUT 256
#define NSEG 64
#define TILE_S 64     // rows of S per block in the segment-reduce kernel
#define TILE_M 16     // segment rows per block in the GEMM kernel

// 8 MB scratch: per-(batch,segment) sums over D_IN. Static device array (no allocs).
__device__ float g_segsum[(size_t)B * NSEG * DIN];

// ---------------------------------------------------------------------------
// Kernel 0: zero the scratch (atomics accumulate into it each launch)
// ---------------------------------------------------------------------------
__global__ void __launch_bounds__(256) zero_kernel() {
    size_t i = (size_t)blockIdx.x * blockDim.x + threadIdx.x;
    reinterpret_cast<float4*>(g_segsum)[i] = make_float4(0.f, 0.f, 0.f, 0.f);
}

// ---------------------------------------------------------------------------
// Kernel 1: segment-reduce enc_output over S.
// Grid: (S/TILE_S, B). Block: 256 threads, each owns 4 consecutive D_IN cols.
// Segment boundaries are uniform across the block -> no divergence.
// ---------------------------------------------------------------------------
__global__ void __launch_bounds__(256) seg_reduce_kernel(
    const float* __restrict__ enc,
    const int*   __restrict__ cls_pos,
    const int*   __restrict__ last_sep)
{
    const int b    = blockIdx.y;
    const int tile = blockIdx.x;
    const int tid  = threadIdx.x;

    __shared__ int sstart[NSEG];
    if (tid < NSEG) sstart[tid] = cls_pos[b * NSEG + tid];
    __syncthreads();

    const int st_last = sstart[NSEG - 1];
    const int e_sep   = last_sep[b] + 1;
    const int end_last = (e_sep > st_last) ? e_sep : S;   // torch last-segment rule

    const int s0 = tile * TILE_S;
    const int s1 = s0 + TILE_S;

    // largest seg with sstart[seg] <= s0 (−1 if none)
    int seg = -1;
    while (seg < NSEG - 1 && sstart[seg + 1] <= s0) seg++;

    const float4* encv = reinterpret_cast<const float4*>(enc)
                       + (size_t)b * S * (DIN / 4) + tid;

    float4 acc = make_float4(0.f, 0.f, 0.f, 0.f);
    int acc_seg = seg;

    int s = s0;
    while (s < s1) {
        while (seg < NSEG - 1 && s >= sstart[seg + 1]) seg++;
        if (seg != acc_seg) {
            if (acc_seg >= 0) {
                float* dst = g_segsum + (size_t)(b * NSEG + acc_seg) * DIN + tid * 4;
                atomicAdd(dst + 0, acc.x);
                atomicAdd(dst + 1, acc.y);
                atomicAdd(dst + 2, acc.z);
                atomicAdd(dst + 3, acc.w);
                acc = make_float4(0.f, 0.f, 0.f, 0.f);
            }
            acc_seg = seg;
        }
        if (seg < 0) {                      // rows before the first CLS: skip
            s = (sstart[0] < s1) ? sstart[0] : s1;
            continue;
        }
        const int nb  = (seg < NSEG - 1) ? sstart[seg + 1] : end_last;
        int lim = (nb < s1) ? nb : s1;
        if (lim <= s) break;                // only seg==last beyond end_last: done

        int k = s;
        for (; k + 4 <= lim; k += 4) {      // MLP=4 fast path
            float4 v0 = encv[(size_t)(k + 0) * (DIN / 4)];
            float4 v1 = encv[(size_t)(k + 1) * (DIN / 4)];
            float4 v2 = encv[(size_t)(k + 2) * (DIN / 4)];
            float4 v3 = encv[(size_t)(k + 3) * (DIN / 4)];
            acc.x += (v0.x + v1.x) + (v2.x + v3.x);
            acc.y += (v0.y + v1.y) + (v2.y + v3.y);
            acc.z += (v0.z + v1.z) + (v2.z + v3.z);
            acc.w += (v0.w + v1.w) + (v2.w + v3.w);
        }
        for (; k < lim; ++k) {
            float4 v = encv[(size_t)k * (DIN / 4)];
            acc.x += v.x; acc.y += v.y; acc.z += v.z; acc.w += v.w;
        }
        s = lim;
    }
    if (acc_seg >= 0) {
        float* dst = g_segsum + (size_t)(b * NSEG + acc_seg) * DIN + tid * 4;
        atomicAdd(dst + 0, acc.x);
        atomicAdd(dst + 1, acc.y);
        atomicAdd(dst + 2, acc.z);
        atomicAdd(dst + 3, acc.w);
    }
}

// ---------------------------------------------------------------------------
// Kernel 2: [2048,1024] @ [1024,256] + count*bias, fused log_softmax over 256.
// Grid: 2048/TILE_M blocks, 256 threads (thread = output column).
// ---------------------------------------------------------------------------
__global__ void __launch_bounds__(256) gemm_lsm_kernel(
    const float* __restrict__ Wm,
    const float* __restrict__ bias,
    const int*   __restrict__ cls_pos,
    const int*   __restrict__ last_sep,
    float*       __restrict__ out)
{
    const int m0 = blockIdx.x * TILE_M;
    const int o  = threadIdx.x;

    // transposed A tile: sAT[k][i], stride 20 floats (80B -> 16B-aligned rows)
    __shared__ float sAT[128][TILE_M + 4];
    __shared__ float sred[8];

    float acc[TILE_M];
#pragma unroll
    for (int i = 0; i < TILE_M; ++i) acc[i] = 0.f;

    for (int kt = 0; kt < DIN / 128; ++kt) {
        __syncthreads();
#pragma unroll
        for (int r = 0; r < (TILE_M * 128) / 256; ++r) {
            int flat = r * 256 + o;
            int i = flat >> 7;
            int k = flat & 127;
            sAT[k][i] = g_segsum[(size_t)(m0 + i) * DIN + kt * 128 + k];
        }
        __syncthreads();

        const float* Wp = Wm + (size_t)(kt * 128) * DOUT + o;
#pragma unroll 4
        for (int k = 0; k < 128; ++k) {
            float w = Wp[(size_t)k * DOUT];
            const float4* ap = reinterpret_cast<const float4*>(&sAT[k][0]);
#pragma unroll
            for (int j = 0; j < TILE_M / 4; ++j) {
                float4 a = ap[j];
                acc[j * 4 + 0] = fmaf(a.x, w, acc[j * 4 + 0]);
                acc[j * 4 + 1] = fmaf(a.y, w, acc[j * 4 + 1]);
                acc[j * 4 + 2] = fmaf(a.z, w, acc[j * 4 + 2]);
                acc[j * 4 + 3] = fmaf(a.w, w, acc[j * 4 + 3]);
            }
        }
    }

    // epilogue: z = acc + count*bias ; out = log_softmax(z) per row
    const float bo  = bias[o];
    const int lane  = o & 31;
    const int wid   = o >> 5;

    for (int i = 0; i < TILE_M; ++i) {
        const int g  = m0 + i;
        const int bb = g >> 6;
        const int nn = g & (NSEG - 1);
        const int start = cls_pos[bb * NSEG + nn];
        int end;
        if (nn < NSEG - 1) end = cls_pos[bb * NSEG + nn + 1];
        else { int e2 = last_sep[bb] + 1; end = (e2 > start) ? e2 : S; }

        const float z = fmaf((float)(end - start), bo, acc[i]);

        // row max over 256 threads
        float m = z;
#pragma unroll
        for (int off = 16; off > 0; off >>= 1)
            m = fmaxf(m, __shfl_xor_sync(0xffffffffu, m, off));
        if (lane == 0) sred[wid] = m;
        __syncthreads();
        m = sred[0];
#pragma unroll
        for (int wj = 1; wj < 8; ++wj) m = fmaxf(m, sred[wj]);
        __syncthreads();   // sred reuse

        // row sum of exp
        float ev = expf(z - m);
        float ssum = ev;
#pragma unroll
        for (int off = 16; off > 0; off >>= 1)
            ssum += __shfl_xor_sync(0xffffffffu, ssum, off);
        if (lane == 0) sred[wid] = ssum;
        __syncthreads();
        float tot = 0.f;
#pragma unroll
        for (int wj = 0; wj < 8; ++wj) tot += sred[wj];

        out[(size_t)g * DOUT + o] = z - m - logf(tot);
        __syncthreads();   // sred reuse for next row
    }
}

// ---------------------------------------------------------------------------
extern "C" void kernel_launch(void* const* d_in, const int* in_sizes, int n_in,
                              void* d_out, int out_size)
{
    // Identify inputs by element count (all sizes are distinct):
    // enc: 32*4096*1024 = 134217728 | W: 1024*256 = 262144 | b: 256
    // max_num_sent: 1 | cls_pos: 32*64 = 2048 | last_sep: 32
    const float* enc  = nullptr;
    const float* Wm   = nullptr;
    const float* bias = nullptr;
    const int*   cls  = nullptr;
    const int*   ls   = nullptr;
    for (int i = 0; i < n_in; ++i) {
        switch (in_sizes[i]) {
            case 134217728: enc  = (const float*)d_in[i]; break;
            case 262144:    Wm   = (const float*)d_in[i]; break;
            case 256:       bias = (const float*)d_in[i]; break;
            case 2048:      cls  = (const int*)d_in[i];   break;
            case 32:        ls   = (const int*)d_in[i];   break;
            default: break;
        }
    }

    // 1) zero scratch (8 MB / 16B = 524288 float4; 2048 blocks x 256)
    zero_kernel<<<2048, 256>>>();

    // 2) segment reduce: grid (64 tiles, 32 batches)
    dim3 g1(S / TILE_S, B);
    seg_reduce_kernel<<<g1, 256>>>(enc, cls, ls);

    // 3) GEMM + bias*count + log_softmax
    gemm_lsm_kernel<<<(B * NSEG) / TILE_M, 256>>>(Wm, bias, cls, ls, (float*)d_out);
}

// round 2
// speedup vs baseline: 1.0537x; 1.0537x over previous
#include <cuda_runtime.h>

#define B 32
#define S 4096
#define DIN 1024
#define DOUT 256
#define NSEG 64
#define TILE_M 16     // segment rows per block in the GEMM kernel

// 8 MB scratch: per-(batch,segment) sums over D_IN. Static device array (no allocs).
__device__ float g_segsum[(size_t)B * NSEG * DIN];

// ---------------------------------------------------------------------------
// Kernel 1: segment-reduce enc_output over S.
// One block per (batch, segment): streams rows [start,end), fully coalesced,
// 8-row unroll for MLP_p1=8, plain vector store (no atomics, no zero pass).
// ---------------------------------------------------------------------------
__global__ void __launch_bounds__(256) seg_reduce_kernel(
    const float* __restrict__ enc,
    const int*   __restrict__ cls_pos,
    const int*   __restrict__ last_sep)
{
    const int b   = blockIdx.x >> 6;
    const int n   = blockIdx.x & (NSEG - 1);
    const int tid = threadIdx.x;

    const int start = cls_pos[b * NSEG + n];
    int end;
    if (n < NSEG - 1) {
        end = cls_pos[b * NSEG + n + 1];
    } else {
        const int e = last_sep[b] + 1;
        end = (e > start) ? e : S;     // torch last-segment rule
    }
    const int len = end - start;

    const float4* __restrict__ p = reinterpret_cast<const float4*>(enc)
                                 + ((size_t)b * S + start) * (DIN / 4) + tid;

    float4 a0 = make_float4(0.f, 0.f, 0.f, 0.f);
    float4 a1 = make_float4(0.f, 0.f, 0.f, 0.f);

    int r = 0;
    for (; r + 8 <= len; r += 8) {
        float4 v0 = p[(size_t)(r + 0) * (DIN / 4)];
        float4 v1 = p[(size_t)(r + 1) * (DIN / 4)];
        float4 v2 = p[(size_t)(r + 2) * (DIN / 4)];
        float4 v3 = p[(size_t)(r + 3) * (DIN / 4)];
        float4 v4 = p[(size_t)(r + 4) * (DIN / 4)];
        float4 v5 = p[(size_t)(r + 5) * (DIN / 4)];
        float4 v6 = p[(size_t)(r + 6) * (DIN / 4)];
        float4 v7 = p[(size_t)(r + 7) * (DIN / 4)];
        a0.x += (v0.x + v1.x) + (v2.x + v3.x);
        a0.y += (v0.y + v1.y) + (v2.y + v3.y);
        a0.z += (v0.z + v1.z) + (v2.z + v3.z);
        a0.w += (v0.w + v1.w) + (v2.w + v3.w);
        a1.x += (v4.x + v5.x) + (v6.x + v7.x);
        a1.y += (v4.y + v5.y) + (v6.y + v7.y);
        a1.z += (v4.z + v5.z) + (v6.z + v7.z);
        a1.w += (v4.w + v5.w) + (v6.w + v7.w);
    }
    for (; r < len; ++r) {
        float4 v = p[(size_t)r * (DIN / 4)];
        a0.x += v.x; a0.y += v.y; a0.z += v.z; a0.w += v.w;
    }
    a0.x += a1.x; a0.y += a1.y; a0.z += a1.z; a0.w += a1.w;

    float4* dst = reinterpret_cast<float4*>(g_segsum) + (size_t)blockIdx.x * (DIN / 4) + tid;
    *dst = a0;
}

// ---------------------------------------------------------------------------
// Kernel 2: [2048,1024] @ [1024,256] + count*bias, fused log_softmax over 256.
// Grid: 128 blocks x 256 threads (thread = output column).
// Packed fp32x2 FMA (fma.rn.f32x2) halves the FFMA pipe floor; k-unroll 8
// front-batches W loads (MLP=8) to hide L2 latency.
// ---------------------------------------------------------------------------
__global__ void __launch_bounds__(256) gemm_lsm_kernel(
    const float* __restrict__ Wm,
    const float* __restrict__ bias,
    const int*   __restrict__ cls_pos,
    const int*   __restrict__ last_sep,
    float*       __restrict__ out)
{
    const int m0 = blockIdx.x * TILE_M;
    const int o  = threadIdx.x;

    // transposed A tile: sAT[k][i], stride 20 floats (80B -> 16B-aligned rows)
    __shared__ float sAT[128][TILE_M + 4];
    __shared__ float sred[8];

    unsigned long long acc2[TILE_M / 2];
#pragma unroll
    for (int q = 0; q < TILE_M / 2; ++q) acc2[q] = 0ull;

    for (int kt = 0; kt < DIN / 128; ++kt) {
        __syncthreads();
#pragma unroll
        for (int r = 0; r < (TILE_M * 128) / 256; ++r) {
            int flat = r * 256 + o;
            int i = flat >> 7;
            int k = flat & 127;
            sAT[k][i] = g_segsum[(size_t)(m0 + i) * DIN + kt * 128 + k];
        }
        __syncthreads();

        const float* Wp = Wm + (size_t)(kt * 128) * DOUT + o;
#pragma unroll 2
        for (int kk = 0; kk < 128; kk += 8) {
            float w[8];
#pragma unroll
            for (int j = 0; j < 8; ++j) w[j] = Wp[(size_t)(kk + j) * DOUT];
#pragma unroll
            for (int j = 0; j < 8; ++j) {
                unsigned long long wp;
                asm("mov.b64 %0, {%1,%1};" : "=l"(wp) : "f"(w[j]));
                const float4* ap = reinterpret_cast<const float4*>(&sAT[kk + j][0]);
#pragma unroll
                for (int q = 0; q < TILE_M / 4; ++q) {
                    float4 a = ap[q];
                    unsigned long long a01, a23;
                    asm("mov.b64 %0, {%1,%2};" : "=l"(a01) : "f"(a.x), "f"(a.y));
                    asm("mov.b64 %0, {%1,%2};" : "=l"(a23) : "f"(a.z), "f"(a.w));
                    asm("fma.rn.f32x2 %0, %1, %2, %3;"
                        : "=l"(acc2[2 * q])     : "l"(a01), "l"(wp), "l"(acc2[2 * q]));
                    asm("fma.rn.f32x2 %0, %1, %2, %3;"
                        : "=l"(acc2[2 * q + 1]) : "l"(a23), "l"(wp), "l"(acc2[2 * q + 1]));
                }
            }
        }
    }

    // unpack packed accumulators
    float acc[TILE_M];
#pragma unroll
    for (int q = 0; q < TILE_M / 2; ++q) {
        float lo, hi;
        asm("mov.b64 {%0,%1}, %2;" : "=f"(lo), "=f"(hi) : "l"(acc2[q]));
        acc[2 * q]     = lo;
        acc[2 * q + 1] = hi;
    }

    // epilogue: z = acc + count*bias ; out = log_softmax(z) per row
    const float bo  = bias[o];
    const int lane  = o & 31;
    const int wid   = o >> 5;

    for (int i = 0; i < TILE_M; ++i) {
        const int g  = m0 + i;
        const int bb = g >> 6;
        const int nn = g & (NSEG - 1);
        const int start = cls_pos[bb * NSEG + nn];
        int end;
        if (nn < NSEG - 1) end = cls_pos[bb * NSEG + nn + 1];
        else { int e2 = last_sep[bb] + 1; end = (e2 > start) ? e2 : S; }

        const float z = fmaf((float)(end - start), bo, acc[i]);

        // row max over 256 threads
        float m = z;
#pragma unroll
        for (int off = 16; off > 0; off >>= 1)
            m = fmaxf(m, __shfl_xor_sync(0xffffffffu, m, off));
        if (lane == 0) sred[wid] = m;
        __syncthreads();
        m = sred[0];
#pragma unroll
        for (int wj = 1; wj < 8; ++wj) m = fmaxf(m, sred[wj]);
        __syncthreads();   // sred reuse

        // row sum of exp
        float ev = expf(z - m);
        float ssum = ev;
#pragma unroll
        for (int off = 16; off > 0; off >>= 1)
            ssum += __shfl_xor_sync(0xffffffffu, ssum, off);
        if (lane == 0) sred[wid] = ssum;
        __syncthreads();
        float tot = 0.f;
#pragma unroll
        for (int wj = 0; wj < 8; ++wj) tot += sred[wj];

        out[(size_t)g * DOUT + o] = z - m - logf(tot);
        __syncthreads();   // sred reuse for next row
    }
}

// ---------------------------------------------------------------------------
extern "C" void kernel_launch(void* const* d_in, const int* in_sizes, int n_in,
                              void* d_out, int out_size)
{
    // Identify inputs by element count (all sizes are distinct):
    // enc: 32*4096*1024 = 134217728 | W: 1024*256 = 262144 | b: 256
    // max_num_sent: 1 | cls_pos: 32*64 = 2048 | last_sep: 32
    const float* enc  = nullptr;
    const float* Wm   = nullptr;
    const float* bias = nullptr;
    const int*   cls  = nullptr;
    const int*   ls   = nullptr;
    for (int i = 0; i < n_in; ++i) {
        switch (in_sizes[i]) {
            case 134217728: enc  = (const float*)d_in[i]; break;
            case 262144:    Wm   = (const float*)d_in[i]; break;
            case 256:       bias = (const float*)d_in[i]; break;
            case 2048:      cls  = (const int*)d_in[i];   break;
            case 32:        ls   = (const int*)d_in[i];   break;
            default: break;
        }
    }

    // 1) segment reduce: one block per (batch, segment) — writes all of g_segsum
    seg_reduce_kernel<<<B * NSEG, 256>>>(enc, cls, ls);

    // 2) GEMM + bias*count + log_softmax
    gemm_lsm_kernel<<<(B * NSEG) / TILE_M, 256>>>(Wm, bias, cls, ls, (float*)d_out);
}

// round 3
// speedup vs baseline: 1.8369x; 1.7433x over previous
#include <cuda_runtime.h>

#define B 32
#define S 4096
#define DIN 1024
#define DOUT 256
#define NSEG 64
#define TILE_S 64     // rows of S per block in the segment-reduce kernel
#define TILE_M 16     // segment rows per block in the GEMM kernel

// 8 MB scratch: per-(batch,segment) sums over D_IN.
__device__ float g_segsum[(size_t)B * NSEG * DIN];

// ---------------------------------------------------------------------------
// Kernel 0: zero the scratch (atomics accumulate into it each launch)
// ---------------------------------------------------------------------------
__global__ void __launch_bounds__(512) zero_kernel() {
    size_t i = (size_t)blockIdx.x * 512 + threadIdx.x;
    reinterpret_cast<float4*>(g_segsum)[i] = make_float4(0.f, 0.f, 0.f, 0.f);
}

// ---------------------------------------------------------------------------
// Kernel 1: segment-reduce enc_output over S — balanced uniform tiles.
// Grid: (S/TILE_S, B), 256 threads; thread owns 4 consecutive D_IN columns.
// Boundaries are uniform across the block (no divergence). Partial sums are
// flushed with RED.F32 atomics into g_segsum. __ldcs: enc has zero reuse.
// ---------------------------------------------------------------------------
__global__ void __launch_bounds__(256) seg_tile_kernel(
    const float* __restrict__ enc,
    const int*   __restrict__ cls_pos,
    const int*   __restrict__ last_sep)
{
    const int b    = blockIdx.y;
    const int tile = blockIdx.x;
    const int tid  = threadIdx.x;

    __shared__ int sstart[NSEG];
    if (tid < NSEG) sstart[tid] = cls_pos[b * NSEG + tid];
    __syncthreads();

    const int st_last  = sstart[NSEG - 1];
    const int e_sep    = last_sep[b] + 1;
    const int end_last = (e_sep > st_last) ? e_sep : S;   // torch last-segment rule

    const int s0 = tile * TILE_S;
    const int s1 = s0 + TILE_S;

    // largest seg with sstart[seg] <= s0 (−1 if none)
    int seg = -1;
    while (seg < NSEG - 1 && sstart[seg + 1] <= s0) seg++;

    const float4* __restrict__ encv = reinterpret_cast<const float4*>(enc)
                                    + (size_t)b * S * (DIN / 4) + tid;

    float4 acc = make_float4(0.f, 0.f, 0.f, 0.f);
    int acc_seg = seg;

    int s = s0;
    while (s < s1) {
        while (seg < NSEG - 1 && s >= sstart[seg + 1]) seg++;
        if (seg != acc_seg) {
            if (acc_seg >= 0) {
                float* dst = g_segsum + (size_t)(b * NSEG + acc_seg) * DIN + tid * 4;
                atomicAdd(dst + 0, acc.x);
                atomicAdd(dst + 1, acc.y);
                atomicAdd(dst + 2, acc.z);
                atomicAdd(dst + 3, acc.w);
                acc = make_float4(0.f, 0.f, 0.f, 0.f);
            }
            acc_seg = seg;
        }
        if (seg < 0) {                      // rows before the first CLS: skip
            s = (sstart[0] < s1) ? sstart[0] : s1;
            continue;
        }
        const int nb  = (seg < NSEG - 1) ? sstart[seg + 1] : end_last;
        int lim = (nb < s1) ? nb : s1;
        if (lim <= s) break;                // only seg==last beyond end_last: done

        int k = s;
        for (; k + 8 <= lim; k += 8) {      // MLP_p1 = 8 fast path
            float4 v0 = __ldcs(&encv[(size_t)(k + 0) * (DIN / 4)]);
            float4 v1 = __ldcs(&encv[(size_t)(k + 1) * (DIN / 4)]);
            float4 v2 = __ldcs(&encv[(size_t)(k + 2) * (DIN / 4)]);
            float4 v3 = __ldcs(&encv[(size_t)(k + 3) * (DIN / 4)]);
            float4 v4 = __ldcs(&encv[(size_t)(k + 4) * (DIN / 4)]);
            float4 v5 = __ldcs(&encv[(size_t)(k + 5) * (DIN / 4)]);
            float4 v6 = __ldcs(&encv[(size_t)(k + 6) * (DIN / 4)]);
            float4 v7 = __ldcs(&encv[(size_t)(k + 7) * (DIN / 4)]);
            acc.x += ((v0.x + v1.x) + (v2.x + v3.x)) + ((v4.x + v5.x) + (v6.x + v7.x));
            acc.y += ((v0.y + v1.y) + (v2.y + v3.y)) + ((v4.y + v5.y) + (v6.y + v7.y));
            acc.z += ((v0.z + v1.z) + (v2.z + v3.z)) + ((v4.z + v5.z) + (v6.z + v7.z));
            acc.w += ((v0.w + v1.w) + (v2.w + v3.w)) + ((v4.w + v5.w) + (v6.w + v7.w));
        }
        for (; k < lim; ++k) {
            float4 v = __ldcs(&encv[(size_t)k * (DIN / 4)]);
            acc.x += v.x; acc.y += v.y; acc.z += v.z; acc.w += v.w;
        }
        s = lim;
    }
    if (acc_seg >= 0) {
        float* dst = g_segsum + (size_t)(b * NSEG + acc_seg) * DIN + tid * 4;
        atomicAdd(dst + 0, acc.x);
        atomicAdd(dst + 1, acc.y);
        atomicAdd(dst + 2, acc.z);
        atomicAdd(dst + 3, acc.w);
    }
}

// ---------------------------------------------------------------------------
// Kernel 2: [2048,1024] @ [1024,256] + count*bias, fused log_softmax over 256.
// 512 threads (16 warps): thread = (k-half, column). Each half accumulates
// over 512 k; halves combine in smem; per-warp (barrier-free) softmax epilogue.
// ---------------------------------------------------------------------------
__global__ void __launch_bounds__(512) gemm_lsm_kernel(
    const float* __restrict__ Wm,
    const float* __restrict__ bias,
    const int*   __restrict__ cls_pos,
    const int*   __restrict__ last_sep,
    float*       __restrict__ out)
{
    const int m0  = blockIdx.x * TILE_M;
    const int tid = threadIdx.x;
    const int col = tid & 255;
    const int h   = tid >> 8;          // k-half: 0 or 1

    __shared__ float sAT[2][128][TILE_M + 4];   // transposed A chunks, 20.5 KB
    __shared__ float sEpi[TILE_M][DOUT];        // combined z values, 16 KB
    __shared__ float sBias[DOUT];

    if (tid < DOUT) sBias[tid] = bias[tid];

    unsigned long long acc2[TILE_M / 2];
#pragma unroll
    for (int q = 0; q < TILE_M / 2; ++q) acc2[q] = 0ull;

    for (int c = 0; c < 4; ++c) {
        __syncthreads();
        // stage 16 rows x 128 k for BOTH halves: 4096 floats, 8 per thread
#pragma unroll
        for (int r = 0; r < 8; ++r) {
            int flat = r * 512 + tid;          // 0..4095
            int hh   = flat >> 11;             // half
            int rem  = flat & 2047;
            int i    = rem >> 7;               // row 0..15
            int k    = rem & 127;
            sAT[hh][k][i] = g_segsum[(size_t)(m0 + i) * DIN + hh * 512 + c * 128 + k];
        }
        __syncthreads();

        const float* Wp = Wm + (size_t)(h * 512 + c * 128) * DOUT + col;
#pragma unroll 2
        for (int kk = 0; kk < 128; kk += 8) {
            float w[8];
#pragma unroll
            for (int j = 0; j < 8; ++j) w[j] = Wp[(size_t)(kk + j) * DOUT];
#pragma unroll
            for (int j = 0; j < 8; ++j) {
                unsigned long long wp;
                asm("mov.b64 %0, {%1,%1};" : "=l"(wp) : "f"(w[j]));
                const ulonglong2* ap =
                    reinterpret_cast<const ulonglong2*>(&sAT[h][kk + j][0]);
#pragma unroll
                for (int q = 0; q < 4; ++q) {
                    ulonglong2 a = ap[q];       // LDS.128 -> two u64 pairs, no movs
                    asm("fma.rn.f32x2 %0, %1, %2, %3;"
                        : "=l"(acc2[2 * q])     : "l"(a.x), "l"(wp), "l"(acc2[2 * q]));
                    asm("fma.rn.f32x2 %0, %1, %2, %3;"
                        : "=l"(acc2[2 * q + 1]) : "l"(a.y), "l"(wp), "l"(acc2[2 * q + 1]));
                }
            }
        }
    }

    // unpack packed accumulators
    float accf[TILE_M];
#pragma unroll
    for (int q = 0; q < TILE_M / 2; ++q) {
        float lo, hi;
        asm("mov.b64 {%0,%1}, %2;" : "=f"(lo), "=f"(hi) : "l"(acc2[q]));
        accf[2 * q] = lo; accf[2 * q + 1] = hi;
    }

    // combine the two k-halves into sEpi
    __syncthreads();
    if (h == 0) {
#pragma unroll
        for (int i = 0; i < TILE_M; ++i) sEpi[i][col] = accf[i];
    }
    __syncthreads();
    if (h == 1) {
#pragma unroll
        for (int i = 0; i < TILE_M; ++i) sEpi[i][col] += accf[i];
    }
    __syncthreads();

    // barrier-free epilogue: warp w owns row w; lane handles 8 columns
    {
        const int wid  = tid >> 5;     // 0..15 == row index
        const int lane = tid & 31;
        const int g  = m0 + wid;
        const int bb = g >> 6;
        const int nn = g & (NSEG - 1);
        const int start = cls_pos[bb * NSEG + nn];
        int end;
        if (nn < NSEG - 1) end = cls_pos[bb * NSEG + nn + 1];
        else { int e2 = last_sep[bb] + 1; end = (e2 > start) ? e2 : S; }
        const float cnt = (float)(end - start);

        float z[8];
        float m = -__int_as_float(0x7f800000);  // -inf
#pragma unroll
        for (int j = 0; j < 8; ++j) {
            int cc = lane + 32 * j;
            z[j] = fmaf(cnt, sBias[cc], sEpi[wid][cc]);
            m = fmaxf(m, z[j]);
        }
#pragma unroll
        for (int off = 16; off > 0; off >>= 1)
            m = fmaxf(m, __shfl_xor_sync(0xffffffffu, m, off));

        float ssum = 0.f;
#pragma unroll
        for (int j = 0; j < 8; ++j) ssum += expf(z[j] - m);
#pragma unroll
        for (int off = 16; off > 0; off >>= 1)
            ssum += __shfl_xor_sync(0xffffffffu, ssum, off);

        const float lse = m + logf(ssum);
        float* op = out + (size_t)g * DOUT;
#pragma unroll
        for (int j = 0; j < 8; ++j)
            op[lane + 32 * j] = z[j] - lse;
    }
}

// ---------------------------------------------------------------------------
extern "C" void kernel_launch(void* const* d_in, const int* in_sizes, int n_in,
                              void* d_out, int out_size)
{
    // Identify inputs by element count (all sizes are distinct):
    // enc: 134217728 | W: 262144 | b: 256 | max_num_sent: 1 | cls_pos: 2048 | last_sep: 32
    const float* enc  = nullptr;
    const float* Wm   = nullptr;
    const float* bias = nullptr;
    const int*   cls  = nullptr;
    const int*   ls   = nullptr;
    for (int i = 0; i < n_in; ++i) {
        switch (in_sizes[i]) {
            case 134217728: enc  = (const float*)d_in[i]; break;
            case 262144:    Wm   = (const float*)d_in[i]; break;
            case 256:       bias = (const float*)d_in[i]; break;
            case 2048:      cls  = (const int*)d_in[i];   break;
            case 32:        ls   = (const int*)d_in[i];   break;
            default: break;
        }
    }

    // 1) zero scratch: 8MB / 16B = 524288 float4 = 1024 blocks x 512
    zero_kernel<<<1024, 512>>>();

    // 2) balanced segment reduce: grid (64 tiles, 32 batches)
    dim3 g1(S / TILE_S, B);
    seg_tile_kernel<<<g1, 256>>>(enc, cls, ls);

    // 3) GEMM + bias*count + log_softmax (512-thread blocks, k-split)
    gemm_lsm_kernel<<<(B * NSEG) / TILE_M, 512>>>(Wm, bias, cls, ls, (float*)d_out);
}

// round 4
// speedup vs baseline: 1.8465x; 1.0052x over previous
#include <cuda_runtime.h>

#define B 32
#define S 4096
#define DIN 1024
#define DOUT 256
#define NSEG 64
#define TILE_S 128    // rows of S per block in the segment-reduce kernel
#define TILE_M 16     // segment rows per block in the GEMM kernel

// 8 MB scratch: per-(batch,segment) sums over D_IN.
// Zero-initialized at module load; gemm_lsm_kernel re-zeroes it every call.
__device__ float g_segsum[(size_t)B * NSEG * DIN];

// ---------------------------------------------------------------------------
// Kernel 1: segment-reduce enc_output over S — balanced uniform tiles.
// Grid: (S/TILE_S, B) = 1024 blocks -> single resident wave at occ>=7.
// 256 threads; thread owns 4 consecutive D_IN columns. Loads are ALWAYS
// 4-row batched (MLP_p1=4); segment bookkeeping happens on registers after
// the loads, so boundaries never drop memory parallelism. Uniform across
// the block -> no divergence. Flushes via RED.F32 atomics.
// ---------------------------------------------------------------------------
__global__ void __launch_bounds__(256, 7) seg_tile_kernel(
    const float* __restrict__ enc,
    const int*   __restrict__ cls_pos,
    const int*   __restrict__ last_sep)
{
    const int b    = blockIdx.y;
    const int tile = blockIdx.x;
    const int tid  = threadIdx.x;

    __shared__ int sstart[NSEG];
    if (tid < NSEG) sstart[tid] = cls_pos[b * NSEG + tid];
    __syncthreads();

    const int e_sep    = last_sep[b] + 1;
    const int end_last = (e_sep > sstart[NSEG - 1]) ? e_sep : S;  // torch rule

    const int s0 = tile * TILE_S;
    const int s1 = s0 + TILE_S;

    // largest seg with sstart[seg] <= s0 (−1 if none); nxt = next boundary
    int seg = -1;
    while (seg < NSEG - 1 && sstart[seg + 1] <= s0) seg++;
    int nxt = (seg < NSEG - 1) ? sstart[seg + 1] : 0x7fffffff;

    const float4* __restrict__ p = reinterpret_cast<const float4*>(enc)
                                 + (size_t)b * S * (DIN / 4) + tid;

    float4 acc = make_float4(0.f, 0.f, 0.f, 0.f);
    int acc_seg = seg;

#define FLUSH_ACC()                                                           \
    do { if (acc_seg >= 0) {                                                  \
        float* d_ = g_segsum + (size_t)(b * NSEG + acc_seg) * DIN + tid * 4;  \
        atomicAdd(d_ + 0, acc.x); atomicAdd(d_ + 1, acc.y);                   \
        atomicAdd(d_ + 2, acc.z); atomicAdd(d_ + 3, acc.w);                   \
    } } while (0)

    for (int base = s0; base < s1; base += 4) {
        float4 v0 = __ldcs(&p[(size_t)(base + 0) * (DIN / 4)]);
        float4 v1 = __ldcs(&p[(size_t)(base + 1) * (DIN / 4)]);
        float4 v2 = __ldcs(&p[(size_t)(base + 2) * (DIN / 4)]);
        float4 v3 = __ldcs(&p[(size_t)(base + 3) * (DIN / 4)]);

        if (seg >= 0 && base + 3 < nxt &&
            (seg < NSEG - 1 || base + 3 < end_last)) {
            // fast path: whole batch inside current (valid) segment
            acc.x += (v0.x + v1.x) + (v2.x + v3.x);
            acc.y += (v0.y + v1.y) + (v2.y + v3.y);
            acc.z += (v0.z + v1.z) + (v2.z + v3.z);
            acc.w += (v0.w + v1.w) + (v2.w + v3.w);
        } else {
            // slow path: per-row bookkeeping on already-loaded registers
            float4 v[4] = {v0, v1, v2, v3};
#pragma unroll
            for (int j = 0; j < 4; ++j) {
                const int r = base + j;
                if (r >= nxt) {
                    while (seg < NSEG - 1 && r >= sstart[seg + 1]) seg++;
                    nxt = (seg < NSEG - 1) ? sstart[seg + 1] : 0x7fffffff;
                    FLUSH_ACC();
                    acc = make_float4(0.f, 0.f, 0.f, 0.f);
                    acc_seg = seg;
                }
                const bool ok = (seg >= 0) && (seg < NSEG - 1 || r < end_last);
                if (ok) {
                    acc.x += v[j].x; acc.y += v[j].y;
                    acc.z += v[j].z; acc.w += v[j].w;
                }
            }
        }
    }
    FLUSH_ACC();
#undef FLUSH_ACC
}

// ---------------------------------------------------------------------------
// Kernel 2: [2048,1024] @ [1024,256] + count*bias, fused log_softmax over 256.
// 1024 threads (32 warps, 8/SMSP): thread = (k-quarter, column); each quarter
// accumulates 256 k with packed fma.rn.f32x2. Quarters combine pairwise in
// smem (2 syncs). Per-warp barrier-free softmax epilogue. Re-zeroes its own
// g_segsum rows (overlapped with last FFMA chunk).
// ---------------------------------------------------------------------------
__global__ void __launch_bounds__(1024) gemm_lsm_kernel(
    const float* __restrict__ Wm,
    const float* __restrict__ bias,
    const int*   __restrict__ cls_pos,
    const int*   __restrict__ last_sep,
    float*       __restrict__ out)
{
    const int m0  = blockIdx.x * TILE_M;
    const int tid = threadIdx.x;
    const int col = tid & 255;
    const int h   = tid >> 8;          // k-quarter: 0..3

    __shared__ float sAT[4][64][TILE_M + 4];   // 20 KB, transposed A chunks
    __shared__ float sEpi[TILE_M][DOUT];       // 16 KB, quarters 0+1
    __shared__ float sBias[DOUT];
    float* sEpi2 = &sAT[0][0][0];              // reuse: quarters 2+3 (16 KB)

    if (tid < DOUT) sBias[tid] = bias[tid];

    unsigned long long acc2[TILE_M / 2];
#pragma unroll
    for (int q = 0; q < TILE_M / 2; ++q) acc2[q] = 0ull;

    for (int c = 0; c < 4; ++c) {
        __syncthreads();
        // stage 16 rows x 64 k for ALL four quarters: 4096 floats, 4/thread
        {
            const int i = (tid >> 6) & 15;
            const int k = tid & 63;
#pragma unroll
            for (int r = 0; r < 4; ++r)
                sAT[r][k][i] = g_segsum[(size_t)(m0 + i) * DIN + r * 256 + c * 64 + k];
        }
        __syncthreads();

        if (c == 3) {
            // all staging reads done: restore g_segsum to zero for next call
            float4* z = reinterpret_cast<float4*>(g_segsum + (size_t)m0 * DIN);
            const float4 zero4 = make_float4(0.f, 0.f, 0.f, 0.f);
#pragma unroll
            for (int r = 0; r < 4; ++r) z[r * 1024 + tid] = zero4;
        }

        const float* Wp = Wm + (size_t)(h * 256 + c * 64) * DOUT + col;
#pragma unroll 2
        for (int kk = 0; kk < 64; kk += 8) {
            float w[8];
#pragma unroll
            for (int j = 0; j < 8; ++j) w[j] = Wp[(size_t)(kk + j) * DOUT];
#pragma unroll
            for (int j = 0; j < 8; ++j) {
                unsigned long long wp;
                asm("mov.b64 %0, {%1,%1};" : "=l"(wp) : "f"(w[j]));
                const ulonglong2* ap =
                    reinterpret_cast<const ulonglong2*>(&sAT[h][kk + j][0]);
#pragma unroll
                for (int q = 0; q < 4; ++q) {
                    ulonglong2 a = ap[q];       // LDS.128 broadcast
                    asm("fma.rn.f32x2 %0, %1, %2, %3;"
                        : "=l"(acc2[2 * q])     : "l"(a.x), "l"(wp), "l"(acc2[2 * q]));
                    asm("fma.rn.f32x2 %0, %1, %2, %3;"
                        : "=l"(acc2[2 * q + 1]) : "l"(a.y), "l"(wp), "l"(acc2[2 * q + 1]));
                }
            }
        }
    }

    // unpack packed accumulators
    float accf[TILE_M];
#pragma unroll
    for (int q = 0; q < TILE_M / 2; ++q) {
        float lo, hi;
        asm("mov.b64 {%0,%1}, %2;" : "=f"(lo), "=f"(hi) : "l"(acc2[q]));
        accf[2 * q] = lo; accf[2 * q + 1] = hi;
    }

    // combine quarters: (0,1) -> sEpi, (2,3) -> sEpi2, two syncs
    __syncthreads();
    if (h == 0) {
#pragma unroll
        for (int i = 0; i < TILE_M; ++i) sEpi[i][col] = accf[i];
    } else if (h == 2) {
#pragma unroll
        for (int i = 0; i < TILE_M; ++i) sEpi2[i * DOUT + col] = accf[i];
    }
    __syncthreads();
    if (h == 1) {
#pragma unroll
        for (int i = 0; i < TILE_M; ++i) sEpi[i][col] += accf[i];
    } else if (h == 3) {
#pragma unroll
        for (int i = 0; i < TILE_M; ++i) sEpi2[i * DOUT + col] += accf[i];
    }
    __syncthreads();

    // barrier-free epilogue: warp w (0..15) owns row w; lane handles 8 cols
    const int wid  = tid >> 5;
    const int lane = tid & 31;
    if (wid < TILE_M) {
        const int g  = m0 + wid;
        const int bb = g >> 6;
        const int nn = g & (NSEG - 1);
        const int start = cls_pos[bb * NSEG + nn];
        int end;
        if (nn < NSEG - 1) end = cls_pos[bb * NSEG + nn + 1];
        else { int e2 = last_sep[bb] + 1; end = (e2 > start) ? e2 : S; }
        const float cnt = (float)(end - start);

        float z[8];
        float m = __int_as_float(0xff800000);  // -inf
#pragma unroll
        for (int j = 0; j < 8; ++j) {
            const int cc = lane + 32 * j;
            z[j] = fmaf(cnt, sBias[cc], sEpi[wid][cc] + sEpi2[wid * DOUT + cc]);
            m = fmaxf(m, z[j]);
        }
#pragma unroll
        for (int off = 16; off > 0; off >>= 1)
            m = fmaxf(m, __shfl_xor_sync(0xffffffffu, m, off));

        float ssum = 0.f;
#pragma unroll
        for (int j = 0; j < 8; ++j) ssum += expf(z[j] - m);
#pragma unroll
        for (int off = 16; off > 0; off >>= 1)
            ssum += __shfl_xor_sync(0xffffffffu, ssum, off);

        const float lse = m + logf(ssum);
        float* op = out + (size_t)g * DOUT;
#pragma unroll
        for (int j = 0; j < 8; ++j)
            op[lane + 32 * j] = z[j] - lse;
    }
}

// ---------------------------------------------------------------------------
extern "C" void kernel_launch(void* const* d_in, const int* in_sizes, int n_in,
                              void* d_out, int out_size)
{
    // Identify inputs by element count (all sizes are distinct):
    // enc: 134217728 | W: 262144 | b: 256 | max_num_sent: 1 | cls_pos: 2048 | last_sep: 32
    const float* enc  = nullptr;
    const float* Wm   = nullptr;
    const float* bias = nullptr;
    const int*   cls  = nullptr;
    const int*   ls   = nullptr;
    for (int i = 0; i < n_in; ++i) {
        switch (in_sizes[i]) {
            case 134217728: enc  = (const float*)d_in[i]; break;
            case 262144:    Wm   = (const float*)d_in[i]; break;
            case 256:       bias = (const float*)d_in[i]; break;
            case 2048:      cls  = (const int*)d_in[i];   break;
            case 32:        ls   = (const int*)d_in[i];   break;
            default: break;
        }
    }

    // 1) balanced segment reduce into (pre-zeroed) g_segsum: single wave
    dim3 g1(S / TILE_S, B);
    seg_tile_kernel<<<g1, 256>>>(enc, cls, ls);

    // 2) GEMM + bias*count + log_softmax; re-zeroes g_segsum for next call
    gemm_lsm_kernel<<<(B * NSEG) / TILE_M, 1024>>>(Wm, bias, cls, ls, (float*)d_out);
}

// round 5
// speedup vs baseline: 2.0423x; 1.1060x over previous
#include <cuda_runtime.h>

#define B 32
#define S 4096
#define DIN 1024
#define DOUT 256
#define NSEG 64
#define TILE_S 128    // rows of S per block in the segment-reduce kernel
#define TILE_M 16     // segment rows per block in the GEMM kernel

// 8 MB scratch: per-(batch,segment) sums over D_IN.
// Zero-initialized at module load; gemm_lsm_kernel re-zeroes it every call.
__device__ float g_segsum[(size_t)B * NSEG * DIN];

// ---------------------------------------------------------------------------
// Kernel 1: segment-reduce enc_output over S — balanced uniform tiles.
// (unchanged from round 4: measured at ~87% of HBM spec)
// ---------------------------------------------------------------------------
__global__ void __launch_bounds__(256, 7) seg_tile_kernel(
    const float* __restrict__ enc,
    const int*   __restrict__ cls_pos,
    const int*   __restrict__ last_sep)
{
    const int b    = blockIdx.y;
    const int tile = blockIdx.x;
    const int tid  = threadIdx.x;

    __shared__ int sstart[NSEG];
    if (tid < NSEG) sstart[tid] = cls_pos[b * NSEG + tid];
    __syncthreads();

    const int e_sep    = last_sep[b] + 1;
    const int end_last = (e_sep > sstart[NSEG - 1]) ? e_sep : S;  // torch rule

    const int s0 = tile * TILE_S;
    const int s1 = s0 + TILE_S;

    int seg = -1;
    while (seg < NSEG - 1 && sstart[seg + 1] <= s0) seg++;
    int nxt = (seg < NSEG - 1) ? sstart[seg + 1] : 0x7fffffff;

    const float4* __restrict__ p = reinterpret_cast<const float4*>(enc)
                                 + (size_t)b * S * (DIN / 4) + tid;

    float4 acc = make_float4(0.f, 0.f, 0.f, 0.f);
    int acc_seg = seg;

#define FLUSH_ACC()                                                           \
    do { if (acc_seg >= 0) {                                                  \
        float* d_ = g_segsum + (size_t)(b * NSEG + acc_seg) * DIN + tid * 4;  \
        atomicAdd(d_ + 0, acc.x); atomicAdd(d_ + 1, acc.y);                   \
        atomicAdd(d_ + 2, acc.z); atomicAdd(d_ + 3, acc.w);                   \
    } } while (0)

    for (int base = s0; base < s1; base += 4) {
        float4 v0 = __ldcs(&p[(size_t)(base + 0) * (DIN / 4)]);
        float4 v1 = __ldcs(&p[(size_t)(base + 1) * (DIN / 4)]);
        float4 v2 = __ldcs(&p[(size_t)(base + 2) * (DIN / 4)]);
        float4 v3 = __ldcs(&p[(size_t)(base + 3) * (DIN / 4)]);

        if (seg >= 0 && base + 3 < nxt &&
            (seg < NSEG - 1 || base + 3 < end_last)) {
            acc.x += (v0.x + v1.x) + (v2.x + v3.x);
            acc.y += (v0.y + v1.y) + (v2.y + v3.y);
            acc.z += (v0.z + v1.z) + (v2.z + v3.z);
            acc.w += (v0.w + v1.w) + (v2.w + v3.w);
        } else {
            float4 v[4] = {v0, v1, v2, v3};
#pragma unroll
            for (int j = 0; j < 4; ++j) {
                const int r = base + j;
                if (r >= nxt) {
                    while (seg < NSEG - 1 && r >= sstart[seg + 1]) seg++;
                    nxt = (seg < NSEG - 1) ? sstart[seg + 1] : 0x7fffffff;
                    FLUSH_ACC();
                    acc = make_float4(0.f, 0.f, 0.f, 0.f);
                    acc_seg = seg;
                }
                const bool ok = (seg >= 0) && (seg < NSEG - 1 || r < end_last);
                if (ok) {
                    acc.x += v[j].x; acc.y += v[j].y;
                    acc.z += v[j].z; acc.w += v[j].w;
                }
            }
        }
    }
    FLUSH_ACC();
#undef FLUSH_ACC
}

// ---------------------------------------------------------------------------
// Kernel 2: [2048,1024] @ [1024,256] + count*bias, fused log_softmax over 256.
// 1024 threads: thread = (k-quarter q, row-half rh, col-pair cp).
// A tile (16x1024) staged ONCE into 80KB dynamic smem (stride 20 -> 4-way STS
// conflicts at stage time only; mainloop reads are warp-broadcast, conflict-
// free). Per k: 2 LDS.128 + 2 movs + 8 packed fma.rn.f32x2 + 1 LDG.64 (W).
// Quarters combine via a 2-round pairwise tree in the same smem. Re-zeroes
// its g_segsum rows. Barrier-free per-warp softmax epilogue.
// ---------------------------------------------------------------------------
__global__ void __launch_bounds__(1024, 1) gemm_lsm_kernel(
    const float* __restrict__ Wm,
    const float* __restrict__ bias,
    const int*   __restrict__ cls_pos,
    const int*   __restrict__ last_sep,
    float*       __restrict__ out)
{
    extern __shared__ float sm[];              // 1024*20 floats = 80KB
    __shared__ float sBias[DOUT];

    const int tid = threadIdx.x;
    const int q   = tid >> 8;                  // k-quarter 0..3  (256 k each)
    const int rh  = (tid >> 7) & 1;            // row half 0..1   (8 rows each)
    const int cp  = tid & 127;                 // col pair 0..127 (2 cols each)
    const int m0  = blockIdx.x * TILE_M;

    if (tid < DOUT) sBias[tid] = bias[tid];

    // ---- stage A transposed: sm[k*20 + i]; warp-consecutive k -> 4-way STS
    {
        const int i  = tid >> 6;               // row 0..15
        const int kl = tid & 63;               // k lane
        const float* src = g_segsum + (size_t)(m0 + i) * DIN + kl;
#pragma unroll
        for (int j = 0; j < 16; ++j)
            sm[(kl + 64 * j) * 20 + i] = src[64 * j];
    }
    __syncthreads();

    // ---- restore g_segsum rows to zero for the next call (fire-and-forget)
    {
        float4* z = reinterpret_cast<float4*>(g_segsum + (size_t)m0 * DIN);
        const float4 z4 = make_float4(0.f, 0.f, 0.f, 0.f);
#pragma unroll
        for (int r = 0; r < 4; ++r) z[r * 1024 + tid] = z4;
    }

    // ---- mainloop: acc2[rp*2+c] = {z[rbase+2rp][c], z[rbase+2rp+1][c]}
    unsigned long long acc2[8];
#pragma unroll
    for (int x = 0; x < 8; ++x) acc2[x] = 0ull;

    const float2* Wp = reinterpret_cast<const float2*>(Wm)
                     + (size_t)(q * 256) * (DOUT / 2) + cp;
    const float* aBase = sm + (size_t)(q * 256) * 20 + rh * 8;

    for (int kk = 0; kk < 256; kk += 4) {
        float2 w[4];
#pragma unroll
        for (int j = 0; j < 4; ++j) w[j] = Wp[(size_t)(kk + j) * (DOUT / 2)];
#pragma unroll
        for (int j = 0; j < 4; ++j) {
            unsigned long long w0p, w1p;
            asm("mov.b64 %0, {%1,%1};" : "=l"(w0p) : "f"(w[j].x));
            asm("mov.b64 %0, {%1,%1};" : "=l"(w1p) : "f"(w[j].y));
            const ulonglong2* ap =
                reinterpret_cast<const ulonglong2*>(aBase + (kk + j) * 20);
            ulonglong2 a01 = ap[0];   // rows rbase+0..3 (two u64 pairs)
            ulonglong2 a23 = ap[1];   // rows rbase+4..7
            asm("fma.rn.f32x2 %0, %1, %2, %3;" : "=l"(acc2[0]) : "l"(a01.x), "l"(w0p), "l"(acc2[0]));
            asm("fma.rn.f32x2 %0, %1, %2, %3;" : "=l"(acc2[1]) : "l"(a01.x), "l"(w1p), "l"(acc2[1]));
            asm("fma.rn.f32x2 %0, %1, %2, %3;" : "=l"(acc2[2]) : "l"(a01.y), "l"(w0p), "l"(acc2[2]));
            asm("fma.rn.f32x2 %0, %1, %2, %3;" : "=l"(acc2[3]) : "l"(a01.y), "l"(w1p), "l"(acc2[3]));
            asm("fma.rn.f32x2 %0, %1, %2, %3;" : "=l"(acc2[4]) : "l"(a23.x), "l"(w0p), "l"(acc2[4]));
            asm("fma.rn.f32x2 %0, %1, %2, %3;" : "=l"(acc2[5]) : "l"(a23.x), "l"(w1p), "l"(acc2[5]));
            asm("fma.rn.f32x2 %0, %1, %2, %3;" : "=l"(acc2[6]) : "l"(a23.y), "l"(w0p), "l"(acc2[6]));
            asm("fma.rn.f32x2 %0, %1, %2, %3;" : "=l"(acc2[7]) : "l"(a23.y), "l"(w1p), "l"(acc2[7]));
        }
    }

    // unpack: accf[r*2+c], r = row within half (0..7), c = col within pair
    float accf[16];
#pragma unroll
    for (int rp = 0; rp < 4; ++rp)
#pragma unroll
        for (int c = 0; c < 2; ++c) {
            float lo, hi;
            asm("mov.b64 {%0,%1}, %2;" : "=f"(lo), "=f"(hi) : "l"(acc2[rp * 2 + c]));
            accf[(2 * rp) * 2 + c]     = lo;
            accf[(2 * rp + 1) * 2 + c] = hi;
        }

    // ---- combine quarters: pairwise tree reusing sm. buf(j,i,c)=sm[j*4096+i*256+c]
    const int rbase = rh * 8;
    const int c0    = cp * 2;

#define WRITE_BUF(jj)                                                          \
    do {                                                                       \
        float2* d_ = reinterpret_cast<float2*>(sm + (jj) * 4096 + c0);         \
        _Pragma("unroll")                                                      \
        for (int r = 0; r < 8; ++r)                                            \
            d_[(rbase + r) * (DOUT / 2) / 1] = make_float2(accf[r*2], accf[r*2+1]); \
    } while (0)

#define ADD_BUF(jj)                                                            \
    do {                                                                       \
        const float2* s_ = reinterpret_cast<const float2*>(sm + (jj) * 4096 + c0); \
        _Pragma("unroll")                                                      \
        for (int r = 0; r < 8; ++r) {                                          \
            float2 v_ = s_[(rbase + r) * (DOUT / 2) / 1];                      \
            accf[r*2] += v_.x; accf[r*2+1] += v_.y;                            \
        }                                                                      \
    } while (0)

    __syncthreads();                 // mainloop done; safe to overwrite sm
    if (q == 2) WRITE_BUF(0);
    if (q == 3) WRITE_BUF(1);
    __syncthreads();
    if (q == 0) ADD_BUF(0);
    if (q == 1) ADD_BUF(1);
    __syncthreads();
    if (q == 1) WRITE_BUF(0);
    __syncthreads();
    if (q == 0) { ADD_BUF(0); WRITE_BUF(1); }   // final z lands in buf 1
    __syncthreads();

#undef WRITE_BUF
#undef ADD_BUF

    // ---- barrier-free epilogue: warp w (0..15) owns row w
    const int wid  = tid >> 5;
    const int lane = tid & 31;
    if (wid < TILE_M) {
        const int g  = m0 + wid;
        const int bb = g >> 6;
        const int nn = g & (NSEG - 1);
        const int start = cls_pos[bb * NSEG + nn];
        int end;
        if (nn < NSEG - 1) end = cls_pos[bb * NSEG + nn + 1];
        else { int e2 = last_sep[bb] + 1; end = (e2 > start) ? e2 : S; }
        const float cnt = (float)(end - start);

        const float* zrow = sm + 4096 + wid * DOUT;

        float z[8];
        float m = __int_as_float(0xff800000);  // -inf
#pragma unroll
        for (int j = 0; j < 8; ++j) {
            const int cc = lane + 32 * j;
            z[j] = fmaf(cnt, sBias[cc], zrow[cc]);
            m = fmaxf(m, z[j]);
        }
#pragma unroll
        for (int off = 16; off > 0; off >>= 1)
            m = fmaxf(m, __shfl_xor_sync(0xffffffffu, m, off));

        float ssum = 0.f;
#pragma unroll
        for (int j = 0; j < 8; ++j) ssum += expf(z[j] - m);
#pragma unroll
        for (int off = 16; off > 0; off >>= 1)
            ssum += __shfl_xor_sync(0xffffffffu, ssum, off);

        const float lse = m + logf(ssum);
        float* op = out + (size_t)g * DOUT;
#pragma unroll
        for (int j = 0; j < 8; ++j)
            op[lane + 32 * j] = z[j] - lse;
    }
}

// ---------------------------------------------------------------------------
extern "C" void kernel_launch(void* const* d_in, const int* in_sizes, int n_in,
                              void* d_out, int out_size)
{
    const float* enc  = nullptr;
    const float* Wm   = nullptr;
    const float* bias = nullptr;
    const int*   cls  = nullptr;
    const int*   ls   = nullptr;
    for (int i = 0; i < n_in; ++i) {
        switch (in_sizes[i]) {
            case 134217728: enc  = (const float*)d_in[i]; break;
            case 262144:    Wm   = (const float*)d_in[i]; break;
            case 256:       bias = (const float*)d_in[i]; break;
            case 2048:      cls  = (const int*)d_in[i];   break;
            case 32:        ls   = (const int*)d_in[i];   break;
            default: break;
        }
    }

    // 1) balanced segment reduce into (pre-zeroed) g_segsum: single wave
    dim3 g1(S / TILE_S, B);
    seg_tile_kernel<<<g1, 256>>>(enc, cls, ls);

    // 2) GEMM + bias*count + log_softmax; 80KB dynamic smem (one-shot A stage)
    const int smem_bytes = 1024 * 20 * (int)sizeof(float);   // 81920
    cudaFuncSetAttribute(gemm_lsm_kernel,
                         cudaFuncAttributeMaxDynamicSharedMemorySize, smem_bytes);
    gemm_lsm_kernel<<<(B * NSEG) / TILE_M, 1024, smem_bytes>>>(
        Wm, bias, cls, ls, (float*)d_out);
}

// round 6
// speedup vs baseline: 2.1813x; 1.0681x over previous
#include <cuda_runtime.h>

#define B 32
#define S 4096
#define DIN 1024
#define DOUT 256
#define NSEG 64
#define TILE_S 128    // rows of S per block in the segment-reduce kernel
#define TILE_M 16     // segment rows per block in the GEMM kernel

// 8 MB scratch: per-(batch,segment) sums over D_IN.
// Zero-initialized at module load; gemm_lsm_kernel re-zeroes it every call.
__device__ float g_segsum[(size_t)B * NSEG * DIN];

// ---------------------------------------------------------------------------
// Kernel 1: segment-reduce enc_output over S — balanced uniform tiles.
// (unchanged: measured ~7 TB/s, at the HBM wall)
// ---------------------------------------------------------------------------
__global__ void __launch_bounds__(256, 7) seg_tile_kernel(
    const float* __restrict__ enc,
    const int*   __restrict__ cls_pos,
    const int*   __restrict__ last_sep)
{
    const int b    = blockIdx.y;
    const int tile = blockIdx.x;
    const int tid  = threadIdx.x;

    __shared__ int sstart[NSEG];
    if (tid < NSEG) sstart[tid] = cls_pos[b * NSEG + tid];
    __syncthreads();

    const int e_sep    = last_sep[b] + 1;
    const int end_last = (e_sep > sstart[NSEG - 1]) ? e_sep : S;  // torch rule

    const int s0 = tile * TILE_S;
    const int s1 = s0 + TILE_S;

    int seg = -1;
    while (seg < NSEG - 1 && sstart[seg + 1] <= s0) seg++;
    int nxt = (seg < NSEG - 1) ? sstart[seg + 1] : 0x7fffffff;

    const float4* __restrict__ p = reinterpret_cast<const float4*>(enc)
                                 + (size_t)b * S * (DIN / 4) + tid;

    float4 acc = make_float4(0.f, 0.f, 0.f, 0.f);
    int acc_seg = seg;

#define FLUSH_ACC()                                                           \
    do { if (acc_seg >= 0) {                                                  \
        float* d_ = g_segsum + (size_t)(b * NSEG + acc_seg) * DIN + tid * 4;  \
        atomicAdd(d_ + 0, acc.x); atomicAdd(d_ + 1, acc.y);                   \
        atomicAdd(d_ + 2, acc.z); atomicAdd(d_ + 3, acc.w);                   \
    } } while (0)

    for (int base = s0; base < s1; base += 4) {
        float4 v0 = __ldcs(&p[(size_t)(base + 0) * (DIN / 4)]);
        float4 v1 = __ldcs(&p[(size_t)(base + 1) * (DIN / 4)]);
        float4 v2 = __ldcs(&p[(size_t)(base + 2) * (DIN / 4)]);
        float4 v3 = __ldcs(&p[(size_t)(base + 3) * (DIN / 4)]);

        if (seg >= 0 && base + 3 < nxt &&
            (seg < NSEG - 1 || base + 3 < end_last)) {
            acc.x += (v0.x + v1.x) + (v2.x + v3.x);
            acc.y += (v0.y + v1.y) + (v2.y + v3.y);
            acc.z += (v0.z + v1.z) + (v2.z + v3.z);
            acc.w += (v0.w + v1.w) + (v2.w + v3.w);
        } else {
            float4 v[4] = {v0, v1, v2, v3};
#pragma unroll
            for (int j = 0; j < 4; ++j) {
                const int r = base + j;
                if (r >= nxt) {
                    while (seg < NSEG - 1 && r >= sstart[seg + 1]) seg++;
                    nxt = (seg < NSEG - 1) ? sstart[seg + 1] : 0x7fffffff;
                    FLUSH_ACC();
                    acc = make_float4(0.f, 0.f, 0.f, 0.f);
                    acc_seg = seg;
                }
                const bool ok = (seg >= 0) && (seg < NSEG - 1 || r < end_last);
                if (ok) {
                    acc.x += v[j].x; acc.y += v[j].y;
                    acc.z += v[j].z; acc.w += v[j].w;
                }
            }
        }
    }
    FLUSH_ACC();
#undef FLUSH_ACC
}

// ---------------------------------------------------------------------------
// Kernel 2: [2048,1024] @ [1024,256] + count*bias, fused log_softmax over 256.
// 512 threads: thread = (k-quarter q, row-half rh, col-quad cq).
// Thread owns 8 rows x 4 cols. Per k: 2 LDS.128 (broadcast) + 1 LDG.128 (W,
// coalesced) + 4 pack movs + 16 packed fma.rn.f32x2 -> LDS pipe no longer
// co-binds with fma. A tile staged once into 80KB dynamic smem (stride 20).
// Quarters combine via 2-round pairwise tree in the same smem. Re-zeroes its
// g_segsum rows. Barrier-free per-warp softmax epilogue (16 warps, 1/row).
// ---------------------------------------------------------------------------
__global__ void __launch_bounds__(512, 1) gemm_lsm_kernel(
    const float* __restrict__ Wm,
    const float* __restrict__ bias,
    const int*   __restrict__ cls_pos,
    const int*   __restrict__ last_sep,
    float*       __restrict__ out)
{
    extern __shared__ float sm[];              // 1024*20 floats = 80KB
    __shared__ float sBias[DOUT];

    const int tid = threadIdx.x;
    const int q   = tid >> 7;                  // k-quarter 0..3 (256 k each)
    const int rh  = (tid >> 6) & 1;            // row half 0..1  (8 rows each)
    const int cq  = tid & 63;                  // col quad 0..63 (4 cols each)
    const int m0  = blockIdx.x * TILE_M;

    if (tid < DOUT) sBias[tid] = bias[tid];

    // ---- stage A transposed: sm[k*20 + i] (one shot, one sync)
    {
        const int i  = tid >> 5;               // row 0..15
        const int kl = tid & 31;               // k lane
        const float* src = g_segsum + (size_t)(m0 + i) * DIN + kl;
#pragma unroll
        for (int j = 0; j < 32; ++j)
            sm[(kl + 32 * j) * 20 + i] = src[32 * j];
    }
    __syncthreads();

    // ---- restore g_segsum rows to zero for the next call (fire-and-forget)
    {
        float4* z = reinterpret_cast<float4*>(g_segsum + (size_t)m0 * DIN);
        const float4 z4 = make_float4(0.f, 0.f, 0.f, 0.f);
#pragma unroll
        for (int r = 0; r < 8; ++r) z[r * 512 + tid] = z4;
    }

    // ---- mainloop: acc2[rp*4+c] = packed rows {2rp, 2rp+1} of column 4cq+c
    unsigned long long acc2[16];
#pragma unroll
    for (int x = 0; x < 16; ++x) acc2[x] = 0ull;

    const float4* Wp = reinterpret_cast<const float4*>(Wm)
                     + (size_t)(q * 256) * (DOUT / 4) + cq;
    const float* aBase = sm + (size_t)(q * 256) * 20 + rh * 8;

    for (int kk = 0; kk < 256; kk += 4) {
        float4 w[4];
#pragma unroll
        for (int j = 0; j < 4; ++j) w[j] = Wp[(size_t)(kk + j) * (DOUT / 4)];
#pragma unroll
        for (int j = 0; j < 4; ++j) {
            const ulonglong2* ap =
                reinterpret_cast<const ulonglong2*>(aBase + (kk + j) * 20);
            ulonglong2 a01 = ap[0];   // row-pairs 0,1 (rows rbase+0..3)
            ulonglong2 a23 = ap[1];   // row-pairs 2,3 (rows rbase+4..7)
            unsigned long long wp0, wp1, wp2, wp3;
            asm("mov.b64 %0, {%1,%1};" : "=l"(wp0) : "f"(w[j].x));
            asm("mov.b64 %0, {%1,%1};" : "=l"(wp1) : "f"(w[j].y));
            asm("mov.b64 %0, {%1,%1};" : "=l"(wp2) : "f"(w[j].z));
            asm("mov.b64 %0, {%1,%1};" : "=l"(wp3) : "f"(w[j].w));
#define FMA2(idx, apair, wpair) \
            asm("fma.rn.f32x2 %0, %1, %2, %3;" : "=l"(acc2[idx]) : "l"(apair), "l"(wpair), "l"(acc2[idx]))
            FMA2(0,  a01.x, wp0); FMA2(1,  a01.x, wp1); FMA2(2,  a01.x, wp2); FMA2(3,  a01.x, wp3);
            FMA2(4,  a01.y, wp0); FMA2(5,  a01.y, wp1); FMA2(6,  a01.y, wp2); FMA2(7,  a01.y, wp3);
            FMA2(8,  a23.x, wp0); FMA2(9,  a23.x, wp1); FMA2(10, a23.x, wp2); FMA2(11, a23.x, wp3);
            FMA2(12, a23.y, wp0); FMA2(13, a23.y, wp1); FMA2(14, a23.y, wp2); FMA2(15, a23.y, wp3);
#undef FMA2
        }
    }

    // unpack: accf[r][c], r = row within half (0..7), c = col within quad
    float accf[8][4];
#pragma unroll
    for (int rp = 0; rp < 4; ++rp)
#pragma unroll
        for (int c = 0; c < 4; ++c) {
            float lo, hi;
            asm("mov.b64 {%0,%1}, %2;" : "=f"(lo), "=f"(hi) : "l"(acc2[rp * 4 + c]));
            accf[2 * rp][c]     = lo;
            accf[2 * rp + 1][c] = hi;
        }

    // ---- combine quarters: pairwise tree reusing sm. buf(j)[16][256]
    const int rbase = rh * 8;
    const int c0    = cq * 4;

#define WRITE_BUF(jj)                                                          \
    do {                                                                       \
        float4* d_ = reinterpret_cast<float4*>(sm + (jj) * 4096 + c0);         \
        _Pragma("unroll")                                                      \
        for (int r = 0; r < 8; ++r)                                            \
            d_[(rbase + r) * (DOUT / 4)] =                                     \
                make_float4(accf[r][0], accf[r][1], accf[r][2], accf[r][3]);   \
    } while (0)

#define ADD_BUF(jj)                                                            \
    do {                                                                       \
        const float4* s_ = reinterpret_cast<const float4*>(sm + (jj) * 4096 + c0); \
        _Pragma("unroll")                                                      \
        for (int r = 0; r < 8; ++r) {                                          \
            float4 v_ = s_[(rbase + r) * (DOUT / 4)];                          \
            accf[r][0] += v_.x; accf[r][1] += v_.y;                            \
            accf[r][2] += v_.z; accf[r][3] += v_.w;                            \
        }                                                                      \
    } while (0)

    __syncthreads();                 // mainloop done; safe to overwrite sm
    if (q == 2) WRITE_BUF(0);
    if (q == 3) WRITE_BUF(1);
    __syncthreads();
    if (q == 0) ADD_BUF(0);
    if (q == 1) ADD_BUF(1);
    __syncthreads();
    if (q == 1) WRITE_BUF(0);
    __syncthreads();
    if (q == 0) { ADD_BUF(0); WRITE_BUF(1); }   // final z lands in buf 1
    __syncthreads();

#undef WRITE_BUF
#undef ADD_BUF

    // ---- barrier-free epilogue: warp w (0..15) owns row w
    const int wid  = tid >> 5;
    const int lane = tid & 31;
    {
        const int g  = m0 + wid;
        const int bb = g >> 6;
        const int nn = g & (NSEG - 1);
        const int start = cls_pos[bb * NSEG + nn];
        int end;
        if (nn < NSEG - 1) end = cls_pos[bb * NSEG + nn + 1];
        else { int e2 = last_sep[bb] + 1; end = (e2 > start) ? e2 : S; }
        const float cnt = (float)(end - start);

        const float* zrow = sm + 4096 + wid * DOUT;

        float z[8];
        float m = __int_as_float(0xff800000);  // -inf
#pragma unroll
        for (int j = 0; j < 8; ++j) {
            const int cc = lane + 32 * j;
            z[j] = fmaf(cnt, sBias[cc], zrow[cc]);
            m = fmaxf(m, z[j]);
        }
#pragma unroll
        for (int off = 16; off > 0; off >>= 1)
            m = fmaxf(m, __shfl_xor_sync(0xffffffffu, m, off));

        float ssum = 0.f;
#pragma unroll
        for (int j = 0; j < 8; ++j) ssum += expf(z[j] - m);
#pragma unroll
        for (int off = 16; off > 0; off >>= 1)
            ssum += __shfl_xor_sync(0xffffffffu, ssum, off);

        const float lse = m + logf(ssum);
        float* op = out + (size_t)g * DOUT;
#pragma unroll
        for (int j = 0; j < 8; ++j)
            op[lane + 32 * j] = z[j] - lse;
    }
}

// ---------------------------------------------------------------------------
extern "C" void kernel_launch(void* const* d_in, const int* in_sizes, int n_in,
                              void* d_out, int out_size)
{
    const float* enc  = nullptr;
    const float* Wm   = nullptr;
    const float* bias = nullptr;
    const int*   cls  = nullptr;
    const int*   ls   = nullptr;
    for (int i = 0; i < n_in; ++i) {
        switch (in_sizes[i]) {
            case 134217728: enc  = (const float*)d_in[i]; break;
            case 262144:    Wm   = (const float*)d_in[i]; break;
            case 256:       bias = (const float*)d_in[i]; break;
            case 2048:      cls  = (const int*)d_in[i];   break;
            case 32:        ls   = (const int*)d_in[i];   break;
            default: break;
        }
    }

    // 1) balanced segment reduce into (pre-zeroed) g_segsum: single wave
    dim3 g1(S / TILE_S, B);
    seg_tile_kernel<<<g1, 256>>>(enc, cls, ls);

    // 2) GEMM + bias*count + log_softmax; 80KB dynamic smem (one-shot A stage)
    const int smem_bytes = 1024 * 20 * (int)sizeof(float);   // 81920
    cudaFuncSetAttribute(gemm_lsm_kernel,
                         cudaFuncAttributeMaxDynamicSharedMemorySize, smem_bytes);
    gemm_lsm_kernel<<<(B * NSEG) / TILE_M, 512, smem_bytes>>>(
        Wm, bias, cls, ls, (float*)d_out);
}